// round 1
// baseline (speedup 1.0000x reference)
#include <cuda_runtime.h>
#include <math.h>

#define Bb 16
#define Cc 64
#define Hh 256
#define Ww 256
#define MM 16   // MX = MY = 16
#define SS 32   // 2*MX kx rows kept

// ---------------- scratch (static device memory; no runtime allocation) ----
__device__ float2 d_tw[256];                 // e^{i 2 pi t/256} = (cos, sin)
__device__ float2 d_Xw[Bb*Cc*Hh*MM];         // [b][c][h][ky]
__device__ float2 d_Xf[Bb*Cc*SS*MM];         // [b][c][kxi][ky]
__device__ float2 d_Y [Bb*Cc*SS*MM];         // [b][o][kxi][ky]
__device__ float2 d_Z [Bb*Hh*Cc*MM];         // [b][h][o][ky]
__device__ float2 d_wt[2*256*4096];          // [half*256+kx*16+ky][i*64+o]
__device__ float  d_partS[Bb*32*Hh];
__device__ float  d_partQ[Bb*32*Hh];
__device__ float2 d_stat[Bb*32];             // (mean, inv_std)

// ---------------- twiddle init ---------------------------------------------
__global__ void k_init_tw() {
    int t = threadIdx.x;
    float s, c;
    sincospif((float)t * (1.0f / 128.0f), &s, &c);   // angle = 2*pi*t/256
    d_tw[t] = make_float2(c, s);
}

// ---------------- weight transpose to mode-major ----------------------------
// dst: d_wt[(half*256 + kx*16 + ky)*4096 + i*64 + o]
__global__ void k_transpose_w(const float* __restrict__ w1r, const float* __restrict__ w1i,
                              const float* __restrict__ w2r, const float* __restrict__ w2i) {
    int n = blockIdx.x * 256 + threadIdx.x;          // 0 .. 2*1048576-1
    int half = n >> 20;
    int rem  = n & ((1 << 20) - 1);
    int mode = rem >> 12;                            // kx*16 + ky
    int io   = rem & 4095;
    int kx = mode >> 4, ky = mode & 15;
    int i = io >> 6, o = io & 63;
    int src = ((i * 64 + o) * 16 + kx) * 16 + ky;    // [Cin][Cout][MX][MY]
    const float* wr = half ? w2r : w1r;
    const float* wi = half ? w2i : w1i;
    d_wt[n] = make_float2(wr[src], wi[src]);
}

// ---------------- stage A: DFT over W, ky in [0,16) -------------------------
__global__ void k_dftW(const float* __restrict__ x) {
    int bc = blockIdx.x;                             // b*64 + c
    __shared__ float2 sT[16 * 256];                  // [ky][w]
    for (int idx = threadIdx.x; idx < 4096; idx += 256) {
        int ky = idx >> 8, w = idx & 255;
        sT[idx] = d_tw[(ky * w) & 255];
    }
    __syncthreads();
    int wid = threadIdx.x >> 5, lane = threadIdx.x & 31;
    for (int h = wid; h < 256; h += 8) {
        const float* xp = x + ((size_t)bc * 256 + h) * 256;
        float xv[8];
#pragma unroll
        for (int j = 0; j < 8; j++) xv[j] = xp[lane + 32 * j];
#pragma unroll
        for (int ky = 0; ky < 16; ky++) {
            float re = 0.f, im = 0.f;
#pragma unroll
            for (int j = 0; j < 8; j++) {
                float2 tv = sT[ky * 256 + lane + 32 * j];
                re = fmaf(xv[j],  tv.x, re);         // e^{-i th}: +cos
                im = fmaf(xv[j], -tv.y, im);         //            -sin
            }
#pragma unroll
            for (int off = 16; off > 0; off >>= 1) {
                re += __shfl_xor_sync(0xffffffffu, re, off);
                im += __shfl_xor_sync(0xffffffffu, im, off);
            }
            if (lane == 0) d_Xw[(bc * 256 + h) * 16 + ky] = make_float2(re, im);
        }
    }
}

// ---------------- stage B: DFT over H, 32 kx rows ----------------------------
__global__ void k_dftH() {
    int bc = blockIdx.x;
    __shared__ float2 sX[4096];                      // [h][ky]
    __shared__ float2 stw[256];
    if (threadIdx.x < 256) stw[threadIdx.x] = d_tw[threadIdx.x];
    for (int idx = threadIdx.x; idx < 4096; idx += 256)
        sX[idx] = d_Xw[bc * 4096 + idx];
    __syncthreads();
#pragma unroll
    for (int rep = 0; rep < 2; rep++) {
        int m = threadIdx.x + rep * 256;             // 0..511
        int kxi = m >> 4, ky = m & 15;
        int kx = (kxi < 16) ? kxi : (224 + kxi);     // bottom rows: H-16+j
        float re = 0.f, im = 0.f;
        int ang = 0;
#pragma unroll 8
        for (int h = 0; h < 256; h++) {
            float2 tv = stw[ang];
            ang = (ang + kx) & 255;
            float2 xv = sX[h * 16 + ky];
            re = fmaf(xv.x, tv.x, re); re = fmaf(xv.y,  tv.y, re);  // (xr+ixi)(c-is)
            im = fmaf(xv.y, tv.x, im); im = fmaf(-xv.x, tv.y, im);
        }
        d_Xf[(bc * 32 + kxi) * 16 + ky] = make_float2(re, im);
    }
}

// ---------------- stage C: per-mode complex channel mix ----------------------
__global__ void k_specmul() {
    int m = blockIdx.x;                              // half*256 + kx*16 + ky
    int half = m >> 8, kx = (m >> 4) & 15, ky = m & 15;
    int kxi = half * 16 + kx;
    __shared__ float2 sX[1024];                      // [b][i]
    __shared__ float2 sW[4096];                      // [i][o]
    for (int idx = threadIdx.x; idx < 1024; idx += 256) {
        int bv = idx >> 6, i = idx & 63;
        sX[idx] = d_Xf[((bv * 64 + i) * 32 + kxi) * 16 + ky];
    }
    for (int idx = threadIdx.x; idx < 4096; idx += 256)
        sW[idx] = d_wt[(size_t)m * 4096 + idx];
    __syncthreads();
#pragma unroll
    for (int k = 0; k < 4; k++) {
        int p = threadIdx.x + k * 256;               // 0..1023
        int bv = p >> 6, o = p & 63;
        float re = 0.f, im = 0.f;
#pragma unroll 16
        for (int i = 0; i < 64; i++) {
            float2 xv = sX[bv * 64 + i];
            float2 wv = sW[i * 64 + o];
            re = fmaf(xv.x, wv.x, re); re = fmaf(-xv.y, wv.y, re);
            im = fmaf(xv.x, wv.y, im); im = fmaf( xv.y, wv.x, im);
        }
        d_Y[((bv * 64 + o) * 32 + kxi) * 16 + ky] = make_float2(re, im);
    }
}

// ---------------- stage D: inverse DFT over H --------------------------------
__global__ void k_idftH() {
    int bc = blockIdx.x;                             // b*64 + o
    int b = bc >> 6, o = bc & 63;
    __shared__ float2 sY[512];                       // [kxi][ky]
    __shared__ float2 stw[256];
    if (threadIdx.x < 256) stw[threadIdx.x] = d_tw[threadIdx.x];
    for (int idx = threadIdx.x; idx < 512; idx += 256)
        sY[idx] = d_Y[bc * 512 + idx];
    __syncthreads();
    int h = threadIdx.x;
    float ar[16], ai[16];
#pragma unroll
    for (int ky = 0; ky < 16; ky++) { ar[ky] = 0.f; ai[ky] = 0.f; }
#pragma unroll
    for (int kxi = 0; kxi < 32; kxi++) {
        int kx = (kxi < 16) ? kxi : (224 + kxi);
        float2 tv = stw[(kx * h) & 255];             // e^{+i th}
#pragma unroll
        for (int ky = 0; ky < 16; ky++) {
            float2 y = sY[kxi * 16 + ky];
            ar[ky] = fmaf(y.x, tv.x, ar[ky]); ar[ky] = fmaf(-y.y, tv.y, ar[ky]);
            ai[ky] = fmaf(y.x, tv.y, ai[ky]); ai[ky] = fmaf( y.y, tv.x, ai[ky]);
        }
    }
#pragma unroll
    for (int ky = 0; ky < 16; ky++) {
        float sc = (ky ? 2.0f : 1.0f) * (1.0f / 65536.0f);   // 1/(H*W), x2 Hermitian
        d_Z[((b * 256 + h) * 64 + o) * 16 + ky] = make_float2(ar[ky] * sc, ai[ky] * sc);
    }
}

// ---------------- stage E: irfftW + 1x1 conv + residual + GELU + partials ----
__global__ void __launch_bounds__(256, 2)
k_fused(const float* __restrict__ x, const float* __restrict__ cw,
        const float* __restrict__ cb, float* __restrict__ out) {
    int h = blockIdx.x, b = blockIdx.y, t = threadIdx.x;
    __shared__ float  sCW[4096];
    __shared__ float  sCB[64];
    __shared__ float2 sZ[1024];                      // [o][ky]
    __shared__ float2 stw[256];
    __shared__ float  wS[256], wQ[256];              // [g][warp]
    for (int idx = t; idx < 4096; idx += 256) sCW[idx] = cw[idx];
    if (t < 64) sCB[t] = cb[t];
    if (t < 256) stw[t] = d_tw[t];
    for (int idx = t; idx < 1024; idx += 256)
        sZ[idx] = d_Z[(size_t)(b * 256 + h) * 1024 + idx];
    __syncthreads();

    size_t base = (size_t)b * 4194304 + (size_t)h * 256 + t;
    float xv[64];
#pragma unroll
    for (int i = 0; i < 64; i++) xv[i] = x[base + (size_t)i * 65536];
    float2 cs[16];
#pragma unroll
    for (int ky = 0; ky < 16; ky++) cs[ky] = stw[(ky * t) & 255];

    int wid = t >> 5, lane = t & 31;
    float pS = 0.f, pQ = 0.f;
#pragma unroll 2
    for (int o = 0; o < 64; o++) {
        float a = sCB[o];
#pragma unroll
        for (int i = 0; i < 64; i++) a = fmaf(sCW[o * 64 + i], xv[i], a);
        float sp = 0.f;
#pragma unroll
        for (int ky = 0; ky < 16; ky++) {
            float2 z = sZ[o * 16 + ky];
            sp = fmaf(z.x, cs[ky].x, sp);
            sp = fmaf(-z.y, cs[ky].y, sp);
        }
        float tv = sp + a + x[base + (size_t)o * 65536];          // L1 hit
        float g  = 0.5f * tv * (1.0f + erff(tv * 0.70710678118654752f));
        out[base + (size_t)o * 65536] = g;
        pS += g; pQ += g * g;
        if (o & 1) {                                 // finished group o>>1
            float s = pS, q = pQ;
#pragma unroll
            for (int off = 16; off > 0; off >>= 1) {
                s += __shfl_xor_sync(0xffffffffu, s, off);
                q += __shfl_xor_sync(0xffffffffu, q, off);
            }
            if (lane == 0) { wS[(o >> 1) * 8 + wid] = s; wQ[(o >> 1) * 8 + wid] = q; }
            pS = 0.f; pQ = 0.f;
        }
    }
    __syncthreads();
    if (t < 32) {                                    // deterministic fixed-order sum
        float s = 0.f, q = 0.f;
#pragma unroll
        for (int k = 0; k < 8; k++) { s += wS[t * 8 + k]; q += wQ[t * 8 + k]; }
        d_partS[(b * 32 + t) * 256 + h] = s;
        d_partQ[(b * 32 + t) * 256 + h] = q;
    }
}

// ---------------- stage R: group statistics ---------------------------------
__global__ void k_stats() {
    int t = threadIdx.x;                             // 512 = (b,g)
    float S = 0.f, Q = 0.f;
    for (int h = 0; h < 256; h++) {
        S += d_partS[t * 256 + h];
        Q += d_partQ[t * 256 + h];
    }
    const float invN = 1.0f / 131072.0f;             // 2 channels * 256 * 256
    float mean = S * invN;
    float var  = Q * invN - mean * mean;
    d_stat[t] = make_float2(mean, 1.0f / sqrtf(var + 1e-5f));
}

// ---------------- stage N: normalize (in place on out) -----------------------
__global__ void k_norm(const float* __restrict__ gnw, const float* __restrict__ gnb,
                       float* __restrict__ out) {
    int idx = blockIdx.x * 256 + threadIdx.x;        // one float4 each
    int e = idx << 2;
    int b = e >> 22;
    int c = (e >> 16) & 63;
    float2 st = d_stat[b * 32 + (c >> 1)];
    float sc = st.y * gnw[c];
    float sh = gnb[c] - st.x * sc;
    float4* o4 = (float4*)out;
    float4 v = o4[idx];
    v.x = fmaf(v.x, sc, sh); v.y = fmaf(v.y, sc, sh);
    v.z = fmaf(v.z, sc, sh); v.w = fmaf(v.w, sc, sh);
    o4[idx] = v;
}

// ---------------- launch -----------------------------------------------------
extern "C" void kernel_launch(void* const* d_in, const int* in_sizes, int n_in,
                              void* d_out, int out_size) {
    const float* x    = (const float*)d_in[0];
    const float* w1r  = (const float*)d_in[1];
    const float* w1i  = (const float*)d_in[2];
    const float* w2r  = (const float*)d_in[3];
    const float* w2i  = (const float*)d_in[4];
    const float* cw   = (const float*)d_in[5];
    const float* cb   = (const float*)d_in[6];
    const float* gnw  = (const float*)d_in[7];
    const float* gnb  = (const float*)d_in[8];
    float* out = (float*)d_out;

    k_init_tw<<<1, 256>>>();
    k_transpose_w<<<8192, 256>>>(w1r, w1i, w2r, w2i);
    k_dftW<<<1024, 256>>>(x);
    k_dftH<<<1024, 256>>>();
    k_specmul<<<512, 256>>>();
    k_idftH<<<1024, 256>>>();
    k_fused<<<dim3(256, 16), 256>>>(x, cw, cb, out);
    k_stats<<<1, 512>>>();
    k_norm<<<65536, 256>>>(gnw, gnb, out);
}

// round 3
// speedup vs baseline: 1.0823x; 1.0823x over previous
#include <cuda_runtime.h>
#include <mma.h>
#include <math.h>
#include <cstdint>

using namespace nvcuda;

#define Bb 16
#define Cc 64
#define Hh 256
#define Ww 256
#define MM 16
#define SS 32

// ---------------- scratch ----------------------------------------------------
__device__ float2 d_tw[256];
__device__ float2 d_Xw[Bb*Cc*Hh*MM];
__device__ float2 d_Xf[Bb*Cc*SS*MM];
__device__ float2 d_Y [Bb*Cc*SS*MM];
__device__ float2 d_Z [Bb*Hh*Cc*MM];
__device__ float2 d_wt[2*256*4096];
__device__ float  d_partS[Bb*32*512];
__device__ float  d_partQ[Bb*32*512];
__device__ float2 d_stat[Bb*32];

__device__ __forceinline__ uint32_t f2tf32(float f) {
    uint32_t r; asm("cvt.rna.tf32.f32 %0, %1;" : "=r"(r) : "f"(f)); return r;
}

// ---------------- twiddle init ------------------------------------------------
__global__ void k_init_tw() {
    int t = threadIdx.x;
    float s, c;
    sincospif((float)t * (1.0f / 128.0f), &s, &c);   // angle = 2*pi*t/256
    d_tw[t] = make_float2(c, s);
}

// ---------------- weight transpose --------------------------------------------
__global__ void k_transpose_w(const float* __restrict__ w1r, const float* __restrict__ w1i,
                              const float* __restrict__ w2r, const float* __restrict__ w2i) {
    int n = blockIdx.x * 256 + threadIdx.x;
    int half = n >> 20;
    int rem  = n & ((1 << 20) - 1);
    int mode = rem >> 12;
    int io   = rem & 4095;
    int kx = mode >> 4, ky = mode & 15;
    int i = io >> 6, o = io & 63;
    int src = ((i * 64 + o) * 16 + kx) * 16 + ky;
    const float* wr = half ? w2r : w1r;
    const float* wi = half ? w2i : w1i;
    d_wt[n] = make_float2(wr[src], wi[src]);
}

// ---------------- stage A: DFT over W -----------------------------------------
__global__ void k_dftW(const float* __restrict__ x) {
    int bc = blockIdx.x;
    __shared__ float2 sT[16 * 256];
    for (int idx = threadIdx.x; idx < 4096; idx += 256) {
        int ky = idx >> 8, w = idx & 255;
        sT[idx] = d_tw[(ky * w) & 255];
    }
    __syncthreads();
    int wid = threadIdx.x >> 5, lane = threadIdx.x & 31;
    for (int h = wid; h < 256; h += 8) {
        const float* xp = x + ((size_t)bc * 256 + h) * 256;
        float xv[8];
#pragma unroll
        for (int j = 0; j < 8; j++) xv[j] = xp[lane + 32 * j];
#pragma unroll
        for (int ky = 0; ky < 16; ky++) {
            float re = 0.f, im = 0.f;
#pragma unroll
            for (int j = 0; j < 8; j++) {
                float2 tv = sT[ky * 256 + lane + 32 * j];
                re = fmaf(xv[j],  tv.x, re);
                im = fmaf(xv[j], -tv.y, im);
            }
#pragma unroll
            for (int off = 16; off > 0; off >>= 1) {
                re += __shfl_xor_sync(0xffffffffu, re, off);
                im += __shfl_xor_sync(0xffffffffu, im, off);
            }
            if (lane == 0) d_Xw[(bc * 256 + h) * 16 + ky] = make_float2(re, im);
        }
    }
}

// ---------------- stage B: DFT over H -----------------------------------------
__global__ void k_dftH() {
    int bc = blockIdx.x;
    __shared__ float2 sX[4096];
    __shared__ float2 stw[256];
    if (threadIdx.x < 256) stw[threadIdx.x] = d_tw[threadIdx.x];
    for (int idx = threadIdx.x; idx < 4096; idx += 256)
        sX[idx] = d_Xw[bc * 4096 + idx];
    __syncthreads();
#pragma unroll
    for (int rep = 0; rep < 2; rep++) {
        int m = threadIdx.x + rep * 256;
        int kxi = m >> 4, ky = m & 15;
        int kx = (kxi < 16) ? kxi : (224 + kxi);
        float re = 0.f, im = 0.f;
        int ang = 0;
#pragma unroll 8
        for (int h = 0; h < 256; h++) {
            float2 tv = stw[ang];
            ang = (ang + kx) & 255;
            float2 xv = sX[h * 16 + ky];
            re = fmaf(xv.x, tv.x, re); re = fmaf(xv.y,  tv.y, re);
            im = fmaf(xv.y, tv.x, im); im = fmaf(-xv.x, tv.y, im);
        }
        d_Xf[(bc * 32 + kxi) * 16 + ky] = make_float2(re, im);
    }
}

// ---------------- stage C: per-mode channel mix --------------------------------
__global__ void k_specmul() {
    int m = blockIdx.x;
    int half = m >> 8, kx = (m >> 4) & 15, ky = m & 15;
    int kxi = half * 16 + kx;
    __shared__ float2 sX[1024];
    __shared__ float2 sW[4096];
    for (int idx = threadIdx.x; idx < 1024; idx += 256) {
        int bv = idx >> 6, i = idx & 63;
        sX[idx] = d_Xf[((bv * 64 + i) * 32 + kxi) * 16 + ky];
    }
    for (int idx = threadIdx.x; idx < 4096; idx += 256)
        sW[idx] = d_wt[(size_t)m * 4096 + idx];
    __syncthreads();
#pragma unroll
    for (int k = 0; k < 4; k++) {
        int p = threadIdx.x + k * 256;
        int bv = p >> 6, o = p & 63;
        float re = 0.f, im = 0.f;
#pragma unroll 16
        for (int i = 0; i < 64; i++) {
            float2 xv = sX[bv * 64 + i];
            float2 wv = sW[i * 64 + o];
            re = fmaf(xv.x, wv.x, re); re = fmaf(-xv.y, wv.y, re);
            im = fmaf(xv.x, wv.y, im); im = fmaf( xv.y, wv.x, im);
        }
        d_Y[((bv * 64 + o) * 32 + kxi) * 16 + ky] = make_float2(re, im);
    }
}

// ---------------- stage D: inverse DFT over H ----------------------------------
__global__ void k_idftH() {
    int bc = blockIdx.x;
    int b = bc >> 6, o = bc & 63;
    __shared__ float2 sY[512];
    __shared__ float2 stw[256];
    if (threadIdx.x < 256) stw[threadIdx.x] = d_tw[threadIdx.x];
    for (int idx = threadIdx.x; idx < 512; idx += 256)
        sY[idx] = d_Y[bc * 512 + idx];
    __syncthreads();
    int h = threadIdx.x;
    float ar[16], ai[16];
#pragma unroll
    for (int ky = 0; ky < 16; ky++) { ar[ky] = 0.f; ai[ky] = 0.f; }
#pragma unroll
    for (int kxi = 0; kxi < 32; kxi++) {
        int kx = (kxi < 16) ? kxi : (224 + kxi);
        float2 tv = stw[(kx * h) & 255];
#pragma unroll
        for (int ky = 0; ky < 16; ky++) {
            float2 y = sY[kxi * 16 + ky];
            ar[ky] = fmaf(y.x, tv.x, ar[ky]); ar[ky] = fmaf(-y.y, tv.y, ar[ky]);
            ai[ky] = fmaf(y.x, tv.y, ai[ky]); ai[ky] = fmaf( y.y, tv.x, ai[ky]);
        }
    }
#pragma unroll
    for (int ky = 0; ky < 16; ky++) {
        float sc = (ky ? 2.0f : 1.0f) * (1.0f / 65536.0f);
        d_Z[((b * 256 + h) * 64 + o) * 16 + ky] = make_float2(ar[ky] * sc, ai[ky] * sc);
    }
}

// ---------------- stage E: wmma tf32 GEMM + epilogue ----------------------------
// Per block: one (b, h, w-half). C[w=128][o=64] = sum_k A[k][w] * B[k][o], K=96.
//   A (col-major): k<64 -> x[i=k][w];  k=64+2ky -> cos(2pi ky w/256); 65+2ky -> sin
//   B (row-major): k<64 -> conv_w[o][k]; 64+2ky -> Zr[o][ky]; 65+2ky -> -Zi[o][ky]
#define LDA 132
#define LDB 72
#define LDC 72
#define SB_OFF  50688                    // 96*132*4
#define RED_OFF 78336                    // SB_OFF + 96*72*4
#define CB_OFF  79360                    // RED_OFF + 1024
#define ESMEM   79616

__global__ void __launch_bounds__(256, 2)
k_fusedE(const float* __restrict__ x, const float* __restrict__ cw,
         const float* __restrict__ cb, float* __restrict__ out) {
    extern __shared__ float sm[];
    float* sA   = sm;                    // [96][132], element (k, w) at sA[k*LDA+w]
    float* sB   = sm + SB_OFF / 4;       // [96][72]
    float* redS = sm + RED_OFF / 4;      // [128]
    float* redQ = redS + 128;
    float* sCB  = sm + CB_OFF / 4;

    int gx = blockIdx.x;
    int h = gx >> 1, wh = gx & 1;
    int b = blockIdx.y, t = threadIdx.x;
    int wid = t >> 5, lane = t & 31;

    // ---- B: conv weights (B[i][o] = cw[o*64+i]) ----
    for (int idx = t; idx < 4096; idx += 256) {
        int o = idx >> 6, i = idx & 63;
        sB[i * LDB + o] = __uint_as_float(f2tf32(cw[idx]));
    }
    // ---- B: Z rows ----
    for (int idx = t; idx < 1024; idx += 256) {
        float2 z = d_Z[(size_t)(b * 256 + h) * 1024 + idx];
        int o = idx >> 4, ky = idx & 15;
        sB[(64 + 2 * ky) * LDB + o] = __uint_as_float(f2tf32(z.x));
        sB[(65 + 2 * ky) * LDB + o] = __uint_as_float(f2tf32(-z.y));
    }
    // ---- A: x slab (coalesced LDG, contiguous STS) ----
    const float* xp = x + (size_t)b * 4194304 + (size_t)h * 256 + wh * 128;
    for (int idx = t; idx < 8192; idx += 256) {
        int i = idx >> 7, wl = idx & 127;
        sA[i * LDA + wl] = __uint_as_float(f2tf32(xp[(size_t)i * 65536 + wl]));
    }
    // ---- A: trig rows ----
    for (int idx = t; idx < 4096; idx += 256) {
        int kk = idx >> 7, wl = idx & 127;
        int ky = kk >> 1;
        int wg = wh * 128 + wl;
        float2 tw = d_tw[(ky * wg) & 255];
        sA[(64 + kk) * LDA + wl] = __uint_as_float(f2tf32((kk & 1) ? tw.y : tw.x));
    }
    if (t < 64) sCB[t] = cb[t];
    __syncthreads();

    // ---- mainloop: each warp owns 16 rows (m), 4 n-tiles ----
    wmma::fragment<wmma::accumulator, 16, 16, 8, float> acc[4];
#pragma unroll
    for (int n0 = 0; n0 < 4; n0++) wmma::fill_fragment(acc[n0], 0.0f);
    int m0 = wid * 16;
#pragma unroll
    for (int k0 = 0; k0 < 12; k0++) {
        wmma::fragment<wmma::matrix_a, 16, 16, 8, wmma::precision::tf32, wmma::col_major> af;
        wmma::load_matrix_sync(af, sA + k0 * 8 * LDA + m0, LDA);
#pragma unroll
        for (int n0 = 0; n0 < 4; n0++) {
            wmma::fragment<wmma::matrix_b, 16, 16, 8, wmma::precision::tf32, wmma::row_major> bf;
            wmma::load_matrix_sync(bf, sB + k0 * 8 * LDB + n0 * 16, LDB);
            wmma::mma_sync(acc[n0], af, bf, acc[n0]);
        }
    }
    __syncthreads();                     // all A reads done before C overwrites sA
    float* sC = sm;                      // [128][72]
#pragma unroll
    for (int n0 = 0; n0 < 4; n0++)
        wmma::store_matrix_sync(sC + m0 * LDC + n0 * 16, acc[n0], LDC, wmma::mem_row_major);
    __syncthreads();

    // ---- epilogue: thread owns (w = t&127, o-half = t>>7) ----
    int tl = t & 127, oh = t >> 7;
    int wg2 = wh * 128 + tl;
    size_t gbase = (size_t)b * 4194304 + (size_t)h * 256 + wg2;
    float pS = 0.f, pQ = 0.f;
#pragma unroll
    for (int j0 = 0; j0 < 8; j0++) {
        float4 c4 = *(float4*)&sC[tl * LDC + oh * 32 + j0 * 4];
        float cv[4] = {c4.x, c4.y, c4.z, c4.w};
#pragma unroll
        for (int u = 0; u < 4; u++) {
            int o = oh * 32 + j0 * 4 + u;
            float v = cv[u] + sCB[o] + x[gbase + (size_t)o * 65536];
            float g = 0.5f * v * (1.0f + erff(v * 0.70710678118654752f));
            out[gbase + (size_t)o * 65536] = g;
            pS += g; pQ += g * g;
            if (u & 1) {
                float s = pS, q = pQ;
#pragma unroll
                for (int off = 16; off > 0; off >>= 1) {
                    s += __shfl_xor_sync(0xffffffffu, s, off);
                    q += __shfl_xor_sync(0xffffffffu, q, off);
                }
                if (lane == 0) {
                    int gi = oh * 16 + j0 * 2 + (u >> 1);
                    redS[gi * 4 + (wid & 3)] = s;
                    redQ[gi * 4 + (wid & 3)] = q;
                }
                pS = 0.f; pQ = 0.f;
            }
        }
    }
    __syncthreads();
    if (t < 32) {
        float s = redS[t * 4] + redS[t * 4 + 1] + redS[t * 4 + 2] + redS[t * 4 + 3];
        float q = redQ[t * 4] + redQ[t * 4 + 1] + redQ[t * 4 + 2] + redQ[t * 4 + 3];
        int slot = h * 2 + wh;
        d_partS[((b * 32 + t) << 9) + slot] = s;
        d_partQ[((b * 32 + t) << 9) + slot] = q;
    }
}

// ---------------- stage R: group statistics -------------------------------------
__global__ void k_stats2() {
    int bg = blockIdx.x;                 // 512 = (b,g)
    int t = threadIdx.x;                 // 512 partials
    __shared__ float rs[16], rq[16];
    float S = d_partS[bg * 512 + t];
    float Q = d_partQ[bg * 512 + t];
#pragma unroll
    for (int off = 16; off > 0; off >>= 1) {
        S += __shfl_xor_sync(0xffffffffu, S, off);
        Q += __shfl_xor_sync(0xffffffffu, Q, off);
    }
    if ((t & 31) == 0) { rs[t >> 5] = S; rq[t >> 5] = Q; }
    __syncthreads();
    if (t == 0) {
        float s = 0.f, q = 0.f;
#pragma unroll
        for (int k = 0; k < 16; k++) { s += rs[k]; q += rq[k]; }
        const float invN = 1.0f / 131072.0f;
        float mean = s * invN;
        float var  = q * invN - mean * mean;
        d_stat[bg] = make_float2(mean, 1.0f / sqrtf(var + 1e-5f));
    }
}

// ---------------- stage N: normalize --------------------------------------------
__global__ void k_norm(const float* __restrict__ gnw, const float* __restrict__ gnb,
                       float* __restrict__ out) {
    int idx = blockIdx.x * 256 + threadIdx.x;
    int e = idx << 2;
    int b = e >> 22;
    int c = (e >> 16) & 63;
    float2 st = d_stat[b * 32 + (c >> 1)];
    float sc = st.y * gnw[c];
    float sh = gnb[c] - st.x * sc;
    float4* o4 = (float4*)out;
    float4 v = o4[idx];
    v.x = fmaf(v.x, sc, sh); v.y = fmaf(v.y, sc, sh);
    v.z = fmaf(v.z, sc, sh); v.w = fmaf(v.w, sc, sh);
    o4[idx] = v;
}

// ---------------- launch ----------------------------------------------------------
extern "C" void kernel_launch(void* const* d_in, const int* in_sizes, int n_in,
                              void* d_out, int out_size) {
    const float* x    = (const float*)d_in[0];
    const float* w1r  = (const float*)d_in[1];
    const float* w1i  = (const float*)d_in[2];
    const float* w2r  = (const float*)d_in[3];
    const float* w2i  = (const float*)d_in[4];
    const float* cw   = (const float*)d_in[5];
    const float* cb   = (const float*)d_in[6];
    const float* gnw  = (const float*)d_in[7];
    const float* gnb  = (const float*)d_in[8];
    float* out = (float*)d_out;

    cudaFuncSetAttribute(k_fusedE, cudaFuncAttributeMaxDynamicSharedMemorySize, ESMEM);

    k_init_tw<<<1, 256>>>();
    k_transpose_w<<<8192, 256>>>(w1r, w1i, w2r, w2i);
    k_dftW<<<1024, 256>>>(x);
    k_dftH<<<1024, 256>>>();
    k_specmul<<<512, 256>>>();
    k_idftH<<<1024, 256>>>();
    k_fusedE<<<dim3(512, 16), 256, ESMEM>>>(x, cw, cb, out);
    k_stats2<<<512, 512>>>();
    k_norm<<<65536, 256>>>(gnw, gnb, out);
}

// round 4
// speedup vs baseline: 1.2543x; 1.1589x over previous
#include <cuda_runtime.h>
#include <mma.h>
#include <math.h>
#include <cstdint>

using namespace nvcuda;

#define Bb 16
#define Cc 64
#define Hh 256
#define Ww 256
#define MM 16
#define SS 32

// ---------------- scratch ----------------------------------------------------
__device__ float2 d_tw[256];
__device__ float  d_TA[32*256];          // forward trig  (cos, -sin) tf32-RNA
__device__ float  d_TE[32*256];          // inverse trig  (cos, +sin) tf32-RNA
__device__ float2 d_Xw[Bb*Cc*Hh*MM];
__device__ float2 d_Xf[Bb*Cc*SS*MM];
__device__ float2 d_Y [Bb*Cc*SS*MM];
__device__ float2 d_Z [Bb*Hh*Cc*MM];
__device__ float2 d_wt[2*256*4096];
__device__ float  d_partS[Bb*32*512];
__device__ float  d_partQ[Bb*32*512];
__device__ float2 d_stat[Bb*32];

__device__ __forceinline__ uint32_t f2tf32(float f) {
    uint32_t r; asm("cvt.rna.tf32.f32 %0, %1;" : "=r"(r) : "f"(f)); return r;
}
__device__ __forceinline__ uint32_t smem_u32(const void* p) {
    uint32_t a;
    asm("{ .reg .u64 t; cvta.to.shared.u64 t, %1; cvt.u32.u64 %0, t; }" : "=r"(a) : "l"(p));
    return a;
}
__device__ __forceinline__ void cp16(uint32_t dst, const void* src) {
    asm volatile("cp.async.cg.shared.global [%0], [%1], 16;" :: "r"(dst), "l"(src));
}
#define CP_COMMIT()  asm volatile("cp.async.commit_group;" ::: "memory")
#define CP_WAIT(n)   asm volatile("cp.async.wait_group %0;" :: "n"(n) : "memory")

// ---------------- init: twiddles + tf32 trig tables ----------------------------
__global__ void k_init() {
    int t = threadIdx.x;
    float s, c;
    sincospif((float)t * (1.0f / 128.0f), &s, &c);
    d_tw[t] = make_float2(c, s);
#pragma unroll
    for (int kk = 0; kk < 32; kk++) {
        int ky = kk >> 1;
        float s2, c2;
        sincospif((float)((ky * t) & 255) * (1.0f / 128.0f), &s2, &c2);
        d_TA[kk * 256 + t] = __uint_as_float(f2tf32((kk & 1) ? -s2 : c2));
        d_TE[kk * 256 + t] = __uint_as_float(f2tf32((kk & 1) ?  s2 : c2));
    }
}

// ---------------- weight transpose --------------------------------------------
__global__ void k_transpose_w(const float* __restrict__ w1r, const float* __restrict__ w1i,
                              const float* __restrict__ w2r, const float* __restrict__ w2i) {
    int n = blockIdx.x * 256 + threadIdx.x;
    int half = n >> 20;
    int rem  = n & ((1 << 20) - 1);
    int mode = rem >> 12;
    int io   = rem & 4095;
    int kx = mode >> 4, ky = mode & 15;
    int i = io >> 6, o = io & 63;
    int src = ((i * 64 + o) * 16 + kx) * 16 + ky;
    const float* wr = half ? w2r : w1r;
    const float* wi = half ? w2i : w1i;
    d_wt[n] = make_float2(wr[src], wi[src]);
}

// ---------------- stage A: DFT over W via tf32 wmma ------------------------------
// Per (b,c): C[ky2=32][h=256] = TA[32][w=256] * X[w][h]  (X read col-major = native)
// smem: xbuf 2*64KB @0, sA 32KB @131072, sC 32x68 @163840. total 172544 B.
#define DW_SMEM 172544
__global__ void __launch_bounds__(256, 1)
k_dftW_tc(const float* __restrict__ x) {
    extern __shared__ float sm[];
    uint32_t sb = smem_u32(sm);
    int bc = blockIdx.x, t = threadIdx.x;
    int wid = t >> 5;
    float* sA = sm + 32768;              // [32][256] row-major
    float* sC = sm + 40960;              // [32][68]
    const float* xblk = x + (size_t)bc * 65536;

    // issue chunk 0 and 1 (each: 64 h-rows x 256 w = 64KB)
#pragma unroll
    for (int c = 0; c < 2; c++) {
#pragma unroll
        for (int j = 0; j < 16; j++) {
            int u = j * 256 + t;
            int hl = u >> 6, wu = u & 63;
            cp16(sb + c * 65536 + u * 16,
                 xblk + (size_t)(c * 64 + hl) * 256 + wu * 4);
        }
        CP_COMMIT();
    }
    // trig table -> smem (plain loads, overlap with cp.async)
    for (int idx = t; idx < 8192; idx += 256) sA[idx] = d_TA[idx];

    int m0 = (wid >> 2) * 16;            // 2 m-tiles
    int n0 = (wid & 3) * 16;             // 4 n-tiles per 64-h chunk

#pragma unroll
    for (int c = 0; c < 4; c++) {
        if (c < 3) { CP_WAIT(1); } else { CP_WAIT(0); }
        __syncthreads();
        float* xb = sm + (c & 1) * 16384;
        wmma::fragment<wmma::accumulator, 16, 16, 8, float> acc;
        wmma::fill_fragment(acc, 0.0f);
#pragma unroll
        for (int k0 = 0; k0 < 32; k0++) {
            wmma::fragment<wmma::matrix_a, 16, 16, 8, wmma::precision::tf32, wmma::row_major> af;
            wmma::fragment<wmma::matrix_b, 16, 16, 8, wmma::precision::tf32, wmma::col_major> bf;
            wmma::load_matrix_sync(af, sA + m0 * 256 + k0 * 8, 256);
            wmma::load_matrix_sync(bf, xb + n0 * 256 + k0 * 8, 256);
            wmma::mma_sync(acc, af, bf, acc);
        }
        __syncthreads();                 // xb reads done; sC safe to overwrite
        if (c + 2 < 4) {                 // refill the buffer just freed
#pragma unroll
            for (int j = 0; j < 16; j++) {
                int u = j * 256 + t;
                int hl = u >> 6, wu = u & 63;
                cp16(sb + (c & 1) * 65536 + u * 16,
                     xblk + (size_t)((c + 2) * 64 + hl) * 256 + wu * 4);
            }
            CP_COMMIT();
        }
        wmma::store_matrix_sync(sC + m0 * 68 + n0, acc, 68, wmma::mem_row_major);
        __syncthreads();
        // write 64 h x 16 ky complex
#pragma unroll
        for (int r = 0; r < 4; r++) {
            int idx = r * 256 + t;
            int ky = idx & 15, hl = idx >> 4;
            float re = sC[(2 * ky) * 68 + hl];
            float im = sC[(2 * ky + 1) * 68 + hl];
            d_Xw[((bc << 8) + c * 64 + hl) * 16 + ky] = make_float2(re, im);
        }
        __syncthreads();
    }
}

// ---------------- stage B: DFT over H (scalar) -----------------------------------
__global__ void k_dftH() {
    int bc = blockIdx.x;
    __shared__ float2 sX[4096];
    __shared__ float2 stw[256];
    if (threadIdx.x < 256) stw[threadIdx.x] = d_tw[threadIdx.x];
    for (int idx = threadIdx.x; idx < 4096; idx += 256)
        sX[idx] = d_Xw[bc * 4096 + idx];
    __syncthreads();
#pragma unroll
    for (int rep = 0; rep < 2; rep++) {
        int m = threadIdx.x + rep * 256;
        int kxi = m >> 4, ky = m & 15;
        int kx = (kxi < 16) ? kxi : (224 + kxi);
        float re = 0.f, im = 0.f;
        int ang = 0;
#pragma unroll 8
        for (int h = 0; h < 256; h++) {
            float2 tv = stw[ang];
            ang = (ang + kx) & 255;
            float2 xv = sX[h * 16 + ky];
            re = fmaf(xv.x, tv.x, re); re = fmaf(xv.y,  tv.y, re);
            im = fmaf(xv.y, tv.x, im); im = fmaf(-xv.x, tv.y, im);
        }
        d_Xf[(bc * 32 + kxi) * 16 + ky] = make_float2(re, im);
    }
}

// ---------------- stage C: per-mode channel mix -----------------------------------
__global__ void k_specmul() {
    int m = blockIdx.x;
    int half = m >> 8, kx = (m >> 4) & 15, ky = m & 15;
    int kxi = half * 16 + kx;
    __shared__ float2 sX[1024];
    __shared__ float2 sW[4096];
    for (int idx = threadIdx.x; idx < 1024; idx += 256) {
        int bv = idx >> 6, i = idx & 63;
        sX[idx] = d_Xf[((bv * 64 + i) * 32 + kxi) * 16 + ky];
    }
    for (int idx = threadIdx.x; idx < 4096; idx += 256)
        sW[idx] = d_wt[(size_t)m * 4096 + idx];
    __syncthreads();
#pragma unroll
    for (int k = 0; k < 4; k++) {
        int p = threadIdx.x + k * 256;
        int bv = p >> 6, o = p & 63;
        float re = 0.f, im = 0.f;
#pragma unroll 16
        for (int i = 0; i < 64; i++) {
            float2 xv = sX[bv * 64 + i];
            float2 wv = sW[i * 64 + o];
            re = fmaf(xv.x, wv.x, re); re = fmaf(-xv.y, wv.y, re);
            im = fmaf(xv.x, wv.y, im); im = fmaf( xv.y, wv.x, im);
        }
        d_Y[((bv * 64 + o) * 32 + kxi) * 16 + ky] = make_float2(re, im);
    }
}

// ---------------- stage D: inverse DFT over H --------------------------------------
__global__ void k_idftH() {
    int bc = blockIdx.x;
    int b = bc >> 6, o = bc & 63;
    __shared__ float2 sY[512];
    __shared__ float2 stw[256];
    if (threadIdx.x < 256) stw[threadIdx.x] = d_tw[threadIdx.x];
    for (int idx = threadIdx.x; idx < 512; idx += 256)
        sY[idx] = d_Y[bc * 512 + idx];
    __syncthreads();
    int h = threadIdx.x;
    float ar[16], ai[16];
#pragma unroll
    for (int ky = 0; ky < 16; ky++) { ar[ky] = 0.f; ai[ky] = 0.f; }
#pragma unroll
    for (int kxi = 0; kxi < 32; kxi++) {
        int kx = (kxi < 16) ? kxi : (224 + kxi);
        float2 tv = stw[(kx * h) & 255];
#pragma unroll
        for (int ky = 0; ky < 16; ky++) {
            float2 y = sY[kxi * 16 + ky];
            ar[ky] = fmaf(y.x, tv.x, ar[ky]); ar[ky] = fmaf(-y.y, tv.y, ar[ky]);
            ai[ky] = fmaf(y.x, tv.y, ai[ky]); ai[ky] = fmaf( y.y, tv.x, ai[ky]);
        }
    }
#pragma unroll
    for (int ky = 0; ky < 16; ky++) {
        float sc = (ky ? 2.0f : 1.0f) * (1.0f / 65536.0f);
        d_Z[((b * 256 + h) * 64 + o) * 16 + ky] = make_float2(ar[ky] * sc, ai[ky] * sc);
    }
}

// ---------------- stage E: pipelined wmma GEMM + epilogue ---------------------------
// Per block (b,h,wh): C[w=128][o=64] = sum_k A[k][w]*B[k][o], K=96 in 3 chunks of 32.
// smem floats: A bufs 2x[32][144] @0 (C [128][72] overlays), B [96][72] @9216,
//              sCB @16128, redS @16192, redQ @16320. total 16448 f = 65792 B.
#define LDA2 144
#define LDB2 72
#define LDC2 72
#define E_SMEM 65792

__global__ void __launch_bounds__(256, 3)
k_fusedE2(const float* __restrict__ x, const float* __restrict__ cw,
          const float* __restrict__ cb, float* __restrict__ out) {
    extern __shared__ float sm[];
    uint32_t sb = smem_u32(sm);
    float* fB   = sm + 9216;
    float* sCB  = sm + 16128;
    float* redS = sm + 16192;
    float* redQ = sm + 16320;

    int gx = blockIdx.x;
    int h = gx >> 1, wh = gx & 1;
    int b = blockIdx.y, t = threadIdx.x;
    int wid = t >> 5, lane = t & 31;

    const float* xbase = x + (size_t)b * 4194304 + (size_t)h * 256 + wh * 128;

    // issue A chunks 0,1 (x channels 0..31, 32..63): 32 rows x 128 floats each
#pragma unroll
    for (int c = 0; c < 2; c++) {
#pragma unroll
        for (int j = 0; j < 4; j++) {
            int u = j * 256 + t;
            int il = u >> 5, w4 = u & 31;
            cp16(sb + (c * 4608 + il * LDA2 + w4 * 4) * 4,
                 xbase + (size_t)(c * 32 + il) * 65536 + w4 * 4);
        }
        CP_COMMIT();
    }

    // build B (conv weights RNA + Z rows RNA) + bias
    for (int idx = t; idx < 4096; idx += 256) {
        int o = idx >> 6, i = idx & 63;
        fB[i * LDB2 + o] = __uint_as_float(f2tf32(cw[idx]));
    }
    for (int idx = t; idx < 1024; idx += 256) {
        float2 z = d_Z[(size_t)(b * 256 + h) * 1024 + idx];
        int o = idx >> 4, ky = idx & 15;
        fB[(64 + 2 * ky) * LDB2 + o] = __uint_as_float(f2tf32(z.x));
        fB[(65 + 2 * ky) * LDB2 + o] = __uint_as_float(f2tf32(-z.y));
    }
    if (t < 64) sCB[t] = cb[t];

    wmma::fragment<wmma::accumulator, 16, 16, 8, float> acc[4];
#pragma unroll
    for (int n0 = 0; n0 < 4; n0++) wmma::fill_fragment(acc[n0], 0.0f);
    int m0 = wid * 16;

    // ---- chunk 0 ----
    CP_WAIT(1);
    __syncthreads();
#pragma unroll
    for (int j = 0; j < 4; j++) {
        wmma::fragment<wmma::matrix_a, 16, 16, 8, wmma::precision::tf32, wmma::col_major> af;
        wmma::load_matrix_sync(af, sm + j * 8 * LDA2 + m0, LDA2);
#pragma unroll
        for (int n0 = 0; n0 < 4; n0++) {
            wmma::fragment<wmma::matrix_b, 16, 16, 8, wmma::precision::tf32, wmma::row_major> bf;
            wmma::load_matrix_sync(bf, fB + j * 8 * LDB2 + n0 * 16, LDB2);
            wmma::mma_sync(acc[n0], af, bf, acc[n0]);
        }
    }
    __syncthreads();                     // buf0 reads done
    // issue chunk 2 (trig table slice) into buf0
#pragma unroll
    for (int j = 0; j < 4; j++) {
        int u = j * 256 + t;
        int kk = u >> 5, w4 = u & 31;
        cp16(sb + (kk * LDA2 + w4 * 4) * 4,
             d_TE + kk * 256 + wh * 128 + w4 * 4);
    }
    CP_COMMIT();

    // ---- chunk 1 ----
    CP_WAIT(1);
    __syncthreads();
#pragma unroll
    for (int j = 0; j < 4; j++) {
        wmma::fragment<wmma::matrix_a, 16, 16, 8, wmma::precision::tf32, wmma::col_major> af;
        wmma::load_matrix_sync(af, sm + 4608 + j * 8 * LDA2 + m0, LDA2);
#pragma unroll
        for (int n0 = 0; n0 < 4; n0++) {
            wmma::fragment<wmma::matrix_b, 16, 16, 8, wmma::precision::tf32, wmma::row_major> bf;
            wmma::load_matrix_sync(bf, fB + (32 + j * 8) * LDB2 + n0 * 16, LDB2);
            wmma::mma_sync(acc[n0], af, bf, acc[n0]);
        }
    }

    // ---- chunk 2 ----
    CP_WAIT(0);
    __syncthreads();
#pragma unroll
    for (int j = 0; j < 4; j++) {
        wmma::fragment<wmma::matrix_a, 16, 16, 8, wmma::precision::tf32, wmma::col_major> af;
        wmma::load_matrix_sync(af, sm + j * 8 * LDA2 + m0, LDA2);
#pragma unroll
        for (int n0 = 0; n0 < 4; n0++) {
            wmma::fragment<wmma::matrix_b, 16, 16, 8, wmma::precision::tf32, wmma::row_major> bf;
            wmma::load_matrix_sync(bf, fB + (64 + j * 8) * LDB2 + n0 * 16, LDB2);
            wmma::mma_sync(acc[n0], af, bf, acc[n0]);
        }
    }
    __syncthreads();                     // all A reads done; C overlays A
    float* sC = sm;
#pragma unroll
    for (int n0 = 0; n0 < 4; n0++)
        wmma::store_matrix_sync(sC + m0 * LDC2 + n0 * 16, acc[n0], LDC2, wmma::mem_row_major);
    __syncthreads();

    // ---- epilogue ----
    int tl = t & 127, oh = t >> 7;
    int wg2 = wh * 128 + tl;
    size_t gbase = (size_t)b * 4194304 + (size_t)h * 256 + wg2;
    float pS = 0.f, pQ = 0.f;
#pragma unroll
    for (int j0 = 0; j0 < 8; j0++) {
        float4 c4 = *(float4*)&sC[tl * LDC2 + oh * 32 + j0 * 4];
        float cv[4] = {c4.x, c4.y, c4.z, c4.w};
#pragma unroll
        for (int u = 0; u < 4; u++) {
            int o = oh * 32 + j0 * 4 + u;
            float v = cv[u] + sCB[o] + x[gbase + (size_t)o * 65536];
            float g = 0.5f * v * (1.0f + erff(v * 0.70710678118654752f));
            out[gbase + (size_t)o * 65536] = g;
            pS += g; pQ += g * g;
            if (u & 1) {
                float s = pS, q = pQ;
#pragma unroll
                for (int off = 16; off > 0; off >>= 1) {
                    s += __shfl_xor_sync(0xffffffffu, s, off);
                    q += __shfl_xor_sync(0xffffffffu, q, off);
                }
                if (lane == 0) {
                    int gi = oh * 16 + j0 * 2 + (u >> 1);
                    redS[gi * 4 + (wid & 3)] = s;
                    redQ[gi * 4 + (wid & 3)] = q;
                }
                pS = 0.f; pQ = 0.f;
            }
        }
    }
    __syncthreads();
    if (t < 32) {
        float s = redS[t * 4] + redS[t * 4 + 1] + redS[t * 4 + 2] + redS[t * 4 + 3];
        float q = redQ[t * 4] + redQ[t * 4 + 1] + redQ[t * 4 + 2] + redQ[t * 4 + 3];
        int slot = h * 2 + wh;
        d_partS[((b * 32 + t) << 9) + slot] = s;
        d_partQ[((b * 32 + t) << 9) + slot] = q;
    }
}

// ---------------- stage R: group statistics ------------------------------------------
__global__ void k_stats2() {
    int bg = blockIdx.x;
    int t = threadIdx.x;
    __shared__ float rs[16], rq[16];
    float S = d_partS[bg * 512 + t];
    float Q = d_partQ[bg * 512 + t];
#pragma unroll
    for (int off = 16; off > 0; off >>= 1) {
        S += __shfl_xor_sync(0xffffffffu, S, off);
        Q += __shfl_xor_sync(0xffffffffu, Q, off);
    }
    if ((t & 31) == 0) { rs[t >> 5] = S; rq[t >> 5] = Q; }
    __syncthreads();
    if (t == 0) {
        float s = 0.f, q = 0.f;
#pragma unroll
        for (int k = 0; k < 16; k++) { s += rs[k]; q += rq[k]; }
        const float invN = 1.0f / 131072.0f;
        float mean = s * invN;
        float var  = q * invN - mean * mean;
        d_stat[bg] = make_float2(mean, 1.0f / sqrtf(var + 1e-5f));
    }
}

// ---------------- stage N: normalize ---------------------------------------------------
__global__ void k_norm(const float* __restrict__ gnw, const float* __restrict__ gnb,
                       float* __restrict__ out) {
    int idx = blockIdx.x * 256 + threadIdx.x;
    int e = idx << 2;
    int b = e >> 22;
    int c = (e >> 16) & 63;
    float2 st = d_stat[b * 32 + (c >> 1)];
    float sc = st.y * gnw[c];
    float sh = gnb[c] - st.x * sc;
    float4* o4 = (float4*)out;
    float4 v = o4[idx];
    v.x = fmaf(v.x, sc, sh); v.y = fmaf(v.y, sc, sh);
    v.z = fmaf(v.z, sc, sh); v.w = fmaf(v.w, sc, sh);
    o4[idx] = v;
}

// ---------------- launch -----------------------------------------------------------------
extern "C" void kernel_launch(void* const* d_in, const int* in_sizes, int n_in,
                              void* d_out, int out_size) {
    const float* x    = (const float*)d_in[0];
    const float* w1r  = (const float*)d_in[1];
    const float* w1i  = (const float*)d_in[2];
    const float* w2r  = (const float*)d_in[3];
    const float* w2i  = (const float*)d_in[4];
    const float* cw   = (const float*)d_in[5];
    const float* cb   = (const float*)d_in[6];
    const float* gnw  = (const float*)d_in[7];
    const float* gnb  = (const float*)d_in[8];
    float* out = (float*)d_out;

    cudaFuncSetAttribute(k_dftW_tc, cudaFuncAttributeMaxDynamicSharedMemorySize, DW_SMEM);
    cudaFuncSetAttribute(k_fusedE2, cudaFuncAttributeMaxDynamicSharedMemorySize, E_SMEM);

    k_init<<<1, 256>>>();
    k_transpose_w<<<8192, 256>>>(w1r, w1i, w2r, w2i);
    k_dftW_tc<<<1024, 256, DW_SMEM>>>(x);
    k_dftH<<<1024, 256>>>();
    k_specmul<<<512, 256>>>();
    k_idftH<<<1024, 256>>>();
    k_fusedE2<<<dim3(512, 16), 256, E_SMEM>>>(x, cw, cb, out);
    k_stats2<<<512, 512>>>();
    k_norm<<<65536, 256>>>(gnw, gnb, out);
}